// round 1
// baseline (speedup 1.0000x reference)
#include <cuda_runtime.h>

#define NMAX 100000
#define EMAX 1600000
#define DD 128
#define NG 512

// ---------------- device scratch (static, no allocs) ----------------
__device__ int   g_is64;
__device__ int   g_cnt[NMAX];
__device__ float g_dis[NMAX];
__device__ int   g_tmp[NMAX];
__device__ int   g_bsum[256];
__device__ int   g_boff[256];
__device__ int   g_rowptr[NMAX + 1];
__device__ int   g_cursor[NMAX];
__device__ int   g_src[EMAX];
__device__ float g_coef[EMAX];
__device__ __align__(256) float g_bufA[(size_t)NMAX * DD];
__device__ __align__(256) float g_bufB[(size_t)NMAX * DD];
__device__ __align__(256) float g_agg[(size_t)NMAX * DD];
__device__ float g_gsum[NG];
__device__ float g_gcnt[NG];

__device__ __forceinline__ int ld_idx(const void* p, long long i) {
    if (g_is64) return (int)((const long long*)p)[i];
    return ((const int*)p)[i];
}

// ---------------- dtype detect ----------------
__global__ void k_detect(const void* ei) {
    if (threadIdx.x == 0) {
        const unsigned long long* p = (const unsigned long long*)ei;
        int ok = 1;
        for (int i = 0; i < 16; i++)
            if (p[i] >> 32) ok = 0;
        g_is64 = ok;  // node ids < 2^31, so int64 => hi words all zero
    }
}

// ---------------- zero counters ----------------
__global__ void k_zero() {
    int i = blockIdx.x * blockDim.x + threadIdx.x;
    if (i < NMAX) g_cnt[i] = 0;
    if (i < NG) { g_gsum[i] = 0.f; g_gcnt[i] = 0.f; }
}

// ---------------- degree count ----------------
__global__ void k_count(const void* ei, int e) {
    int i = blockIdx.x * blockDim.x + threadIdx.x;
    if (i < e) {
        int d = ld_idx(ei, (long long)e + i);
        atomicAdd(&g_cnt[d], 1);
    }
}

__global__ void k_dis(int n) {
    int i = blockIdx.x * blockDim.x + threadIdx.x;
    if (i < n) g_dis[i] = rsqrtf((float)g_cnt[i] + 1.0f);
}

// ---------------- scan (3 phases) ----------------
__global__ void k_scan1(int n) {
    __shared__ int s[512];
    int t = threadIdx.x;
    int i = blockIdx.x * 512 + t;
    int v = (i < n) ? g_cnt[i] : 0;
    s[t] = v;
    __syncthreads();
    for (int off = 1; off < 512; off <<= 1) {
        int x = 0;
        if (t >= off) x = s[t - off];
        __syncthreads();
        s[t] += x;
        __syncthreads();
    }
    if (i < n) g_tmp[i] = s[t];
    if (t == 511) g_bsum[blockIdx.x] = s[511];
}

__global__ void k_scan2(int nb, int n) {
    __shared__ int s[256];
    int t = threadIdx.x;
    int v = (t < nb) ? g_bsum[t] : 0;
    s[t] = v;
    __syncthreads();
    for (int off = 1; off < 256; off <<= 1) {
        int x = 0;
        if (t >= off) x = s[t - off];
        __syncthreads();
        s[t] += x;
        __syncthreads();
    }
    g_boff[t] = s[t] - v;  // exclusive
    if (t == 255) g_rowptr[n] = s[255];
}

__global__ void k_scan3(int n) {
    int t = threadIdx.x;
    int i = blockIdx.x * 512 + t;
    if (i < n) {
        int rp = g_tmp[i] - g_cnt[i] + g_boff[blockIdx.x];
        g_rowptr[i] = rp;
        g_cursor[i] = rp;
    }
}

// ---------------- CSR fill ----------------
__global__ void k_fill(const void* ei, int e) {
    int i = blockIdx.x * blockDim.x + threadIdx.x;
    if (i < e) {
        int s = ld_idx(ei, i);
        int d = ld_idx(ei, (long long)e + i);
        int pos = atomicAdd(&g_cursor[d], 1);
        g_src[pos] = s;
        g_coef[pos] = g_dis[s] * g_dis[d];
    }
}

// ---------------- aggregation: warp per node, float4 per lane ----------------
__global__ void k_agg(const float* __restrict__ x, int insel, int n) {
    int gt = blockIdx.x * blockDim.x + threadIdx.x;
    int w = gt >> 5;
    int lane = gt & 31;
    if (w >= n) return;
    const float* in = (insel == 0) ? x : ((insel == 1) ? g_bufA : g_bufB);
    const float4* in4 = (const float4*)in;

    float ds = g_dis[w];
    float self = ds * ds;
    float4 a = in4[(size_t)w * 32 + lane];
    float4 acc;
    acc.x = a.x * self; acc.y = a.y * self; acc.z = a.z * self; acc.w = a.w * self;

    int beg = g_rowptr[w], end = g_rowptr[w + 1];
    for (int base = beg; base < end; base += 32) {
        int e = base + lane;
        int s = 0; float c = 0.f;
        if (e < end) { s = g_src[e]; c = g_coef[e]; }
        int m = min(32, end - base);
        int k = 0;
        for (; k + 4 <= m; k += 4) {
            int s0 = __shfl_sync(0xffffffffu, s, k);
            int s1 = __shfl_sync(0xffffffffu, s, k + 1);
            int s2 = __shfl_sync(0xffffffffu, s, k + 2);
            int s3 = __shfl_sync(0xffffffffu, s, k + 3);
            float c0 = __shfl_sync(0xffffffffu, c, k);
            float c1 = __shfl_sync(0xffffffffu, c, k + 1);
            float c2 = __shfl_sync(0xffffffffu, c, k + 2);
            float c3 = __shfl_sync(0xffffffffu, c, k + 3);
            float4 v0 = in4[(size_t)s0 * 32 + lane];
            float4 v1 = in4[(size_t)s1 * 32 + lane];
            float4 v2 = in4[(size_t)s2 * 32 + lane];
            float4 v3 = in4[(size_t)s3 * 32 + lane];
            acc.x += c0 * v0.x; acc.y += c0 * v0.y; acc.z += c0 * v0.z; acc.w += c0 * v0.w;
            acc.x += c1 * v1.x; acc.y += c1 * v1.y; acc.z += c1 * v1.z; acc.w += c1 * v1.w;
            acc.x += c2 * v2.x; acc.y += c2 * v2.y; acc.z += c2 * v2.z; acc.w += c2 * v2.w;
            acc.x += c3 * v3.x; acc.y += c3 * v3.y; acc.z += c3 * v3.z; acc.w += c3 * v3.w;
        }
        for (; k < m; k++) {
            int ss = __shfl_sync(0xffffffffu, s, k);
            float cc = __shfl_sync(0xffffffffu, c, k);
            float4 v = in4[(size_t)ss * 32 + lane];
            acc.x += cc * v.x; acc.y += cc * v.y; acc.z += cc * v.z; acc.w += cc * v.w;
        }
    }
    float4* out4 = (float4*)g_agg;
    out4[(size_t)w * 32 + lane] = acc;
}

// ---------------- fused GEMM + bias + LN + residual + ReLU ----------------
// 32 rows x 128 cols per block. 256 threads: thread t -> cg = t&31 (4 cols),
// rg = t>>5 (warp, 4 rows). W in smem (reused across rows), A transposed k-major.
__global__ __launch_bounds__(256, 2) void k_transform(
    const float* __restrict__ Ws, const float* __restrict__ bs,
    const float* __restrict__ gammas, const float* __restrict__ betas,
    int layer, int ressel, int outsel, int dorelu, int n)
{
    __shared__ __align__(16) float sW[DD * DD];     // 64KB
    __shared__ __align__(16) float sA[DD][36];      // 18KB, k-major, padded

    int t = threadIdx.x;
    const float* W = Ws + (size_t)layer * DD * DD;
    const float4* W4 = (const float4*)W;
    float4* sW4 = (float4*)sW;
#pragma unroll
    for (int i = 0; i < 16; i++) sW4[t + i * 256] = W4[t + i * 256];

    int row0 = blockIdx.x * 32;
    for (int i = t; i < 32 * DD; i += 256) {
        int r = i >> 7, k = i & 127;
        int row = row0 + r;
        sA[k][r] = (row < n) ? g_agg[(size_t)row * DD + k] : 0.f;
    }
    __syncthreads();

    int cg = t & 31;   // column group: cols cg*4..cg*4+3
    int rg = t >> 5;   // row group (== warp id): rows rg*4..rg*4+3

    float acc[4][4] = {};
#pragma unroll 8
    for (int k = 0; k < DD; k++) {
        float4 wv = *(const float4*)&sW[k * DD + cg * 4];
        float4 av = *(const float4*)&sA[k][rg * 4];
        acc[0][0] += av.x * wv.x; acc[0][1] += av.x * wv.y; acc[0][2] += av.x * wv.z; acc[0][3] += av.x * wv.w;
        acc[1][0] += av.y * wv.x; acc[1][1] += av.y * wv.y; acc[1][2] += av.y * wv.z; acc[1][3] += av.y * wv.w;
        acc[2][0] += av.z * wv.x; acc[2][1] += av.z * wv.y; acc[2][2] += av.z * wv.z; acc[2][3] += av.z * wv.w;
        acc[3][0] += av.w * wv.x; acc[3][1] += av.w * wv.y; acc[3][2] += av.w * wv.z; acc[3][3] += av.w * wv.w;
    }

    float4 bv = ((const float4*)(bs + (size_t)layer * DD))[cg];
#pragma unroll
    for (int r = 0; r < 4; r++) {
        acc[r][0] += bv.x; acc[r][1] += bv.y; acc[r][2] += bv.z; acc[r][3] += bv.w;
    }

    float4 gv = ((const float4*)(gammas + (size_t)layer * DD))[cg];
    float4 bev = ((const float4*)(betas + (size_t)layer * DD))[cg];
    const float4* res4 = (ressel == 1) ? (const float4*)g_bufA
                       : (ressel == 2) ? (const float4*)g_bufB : (const float4*)0;
    float4* out4 = (outsel == 1) ? (float4*)g_bufA : (float4*)g_bufB;

#pragma unroll
    for (int r = 0; r < 4; r++) {
        int row = row0 + rg * 4 + r;
        float s = acc[r][0] + acc[r][1] + acc[r][2] + acc[r][3];
        float q = acc[r][0] * acc[r][0] + acc[r][1] * acc[r][1]
                + acc[r][2] * acc[r][2] + acc[r][3] * acc[r][3];
#pragma unroll
        for (int o = 16; o > 0; o >>= 1) {
            s += __shfl_xor_sync(0xffffffffu, s, o);
            q += __shfl_xor_sync(0xffffffffu, q, o);
        }
        float mu = s * (1.0f / 128.0f);
        float var = q * (1.0f / 128.0f) - mu * mu;
        float isd = rsqrtf(var + 1e-5f);
        float4 o4;
        o4.x = (acc[r][0] - mu) * isd * gv.x + bev.x;
        o4.y = (acc[r][1] - mu) * isd * gv.y + bev.y;
        o4.z = (acc[r][2] - mu) * isd * gv.z + bev.z;
        o4.w = (acc[r][3] - mu) * isd * gv.w + bev.w;
        if (row < n) {
            if (res4) {
                float4 rv = res4[(size_t)row * 32 + cg];
                o4.x += rv.x; o4.y += rv.y; o4.z += rv.z; o4.w += rv.w;
            }
            if (dorelu) {
                o4.x = fmaxf(o4.x, 0.f); o4.y = fmaxf(o4.y, 0.f);
                o4.z = fmaxf(o4.z, 0.f); o4.w = fmaxf(o4.w, 0.f);
            }
            out4[(size_t)row * 32 + cg] = o4;
        }
    }
}

// ---------------- pooling ----------------
__global__ void k_pool(const float* __restrict__ lin_w, const void* batch, int hsel, int n) {
    int gt = blockIdx.x * blockDim.x + threadIdx.x;
    int w = gt >> 5;
    int lane = gt & 31;
    if (w >= n) return;
    const float4* h4 = (hsel == 1) ? (const float4*)g_bufA : (const float4*)g_bufB;
    float4 h = h4[(size_t)w * 32 + lane];
    float4 wv = ((const float4*)lin_w)[lane];
    float p = h.x * wv.x + h.y * wv.y + h.z * wv.z + h.w * wv.w;
#pragma unroll
    for (int o = 16; o > 0; o >>= 1) p += __shfl_xor_sync(0xffffffffu, p, o);
    if (lane == 0) {
        int g = ld_idx(batch, w);
        atomicAdd(&g_gsum[g], p);
        atomicAdd(&g_gcnt[g], 1.f);
    }
}

__global__ void k_final(const float* __restrict__ lin_b, float* __restrict__ out) {
    int g = blockIdx.x * blockDim.x + threadIdx.x;
    if (g < NG) out[g] = g_gsum[g] / fmaxf(g_gcnt[g], 1.f) + lin_b[0];
}

// ---------------- launch ----------------
extern "C" void kernel_launch(void* const* d_in, const int* in_sizes, int n_in,
                              void* d_out, int out_size) {
    const float* x      = (const float*)d_in[0];
    const void*  ei     = d_in[1];
    const void*  batch  = d_in[2];
    const float* Ws     = (const float*)d_in[3];
    const float* bs     = (const float*)d_in[4];
    const float* gammas = (const float*)d_in[5];
    const float* betas  = (const float*)d_in[6];
    const float* lin_w  = (const float*)d_in[7];
    const float* lin_b  = (const float*)d_in[8];

    int n = in_sizes[0] / DD;   // 100000
    int e = in_sizes[1] / 2;    // 1600000

    k_detect<<<1, 32>>>(ei);
    k_zero<<<(NMAX + 255) / 256, 256>>>();
    k_count<<<(e + 255) / 256, 256>>>(ei, e);
    k_dis<<<(n + 255) / 256, 256>>>(n);

    int nb = (n + 511) / 512;
    k_scan1<<<nb, 512>>>(n);
    k_scan2<<<1, 256>>>(nb, n);
    k_scan3<<<nb, 512>>>(n);
    k_fill<<<(e + 255) / 256, 256>>>(ei, e);

    int aggblocks = (n * 32 + 255) / 256;
    int tblocks = (n + 31) / 32;

    // layer 0: in=x, out=A, relu, no residual
    k_agg<<<aggblocks, 256>>>(x, 0, n);
    k_transform<<<tblocks, 256>>>(Ws, bs, gammas, betas, 0, 0, 1, 1, n);
    // layer 1: in=A, res=A, out=B, relu
    k_agg<<<aggblocks, 256>>>(x, 1, n);
    k_transform<<<tblocks, 256>>>(Ws, bs, gammas, betas, 1, 1, 2, 1, n);
    // layer 2: in=B, res=B, out=A, relu
    k_agg<<<aggblocks, 256>>>(x, 2, n);
    k_transform<<<tblocks, 256>>>(Ws, bs, gammas, betas, 2, 2, 1, 1, n);
    // layer 3: in=A, res=A, out=B, NO relu
    k_agg<<<aggblocks, 256>>>(x, 1, n);
    k_transform<<<tblocks, 256>>>(Ws, bs, gammas, betas, 3, 1, 2, 0, n);

    k_pool<<<aggblocks, 256>>>(lin_w, batch, 2, n);
    k_final<<<2, 256>>>(lin_b, (float*)d_out);
}